// round 8
// baseline (speedup 1.0000x reference)
#include <cuda_runtime.h>
#include <cstdint>

#define EPSF 1e-5f

// ---------------- scratch (device globals; no allocation allowed) -------------
// B=4, C=2048, R=512, H=W=64, N=4096
__device__ float g_f   [4L*512*4096];     // 32 MB
__device__ float g_q   [4L*512*4096];
__device__ float g_kk  [4L*512*4096];
__device__ float g_v   [4L*512*4096];
__device__ float g_upd [4L*512*4096];
__device__ float g_attn[4L*4096*4096];    // 268 MB

// ---------------- tf32 helpers -------------------------------------------------
__device__ __forceinline__ uint32_t f2tf32(float x) {
    uint32_t r;
    asm("cvt.rna.tf32.f32 %0, %1;" : "=r"(r) : "f"(x));
    return r;
}
// split x into tf32 hi + tf32 lo (x ~= hi + lo to ~22 mantissa bits)
__device__ __forceinline__ void tf32_split(float x, uint32_t& hi, uint32_t& lo) {
    hi = f2tf32(x);
    lo = f2tf32(x - __uint_as_float(hi));
}

__device__ __forceinline__ void mma8(float* c,
                                     uint32_t a0, uint32_t a1, uint32_t a2, uint32_t a3,
                                     uint32_t b0, uint32_t b1) {
    asm volatile(
        "mma.sync.aligned.m16n8k8.row.col.f32.tf32.tf32.f32 "
        "{%0,%1,%2,%3}, {%4,%5,%6,%7}, {%8,%9}, {%0,%1,%2,%3};"
        : "+f"(c[0]), "+f"(c[1]), "+f"(c[2]), "+f"(c[3])
        : "r"(a0), "r"(a1), "r"(a2), "r"(a3), "r"(b0), "r"(b1));
}

// ---------------- tensor-core GEMM ---------------------------------------------
// C[m][n] = sum_k A(m,k) * B(k,n)   (+ optional B2 fused add, + optional BN+ReLU)
// AMODE 0: A stored [m][k], k contiguous.  AMODE 1: A stored [k][m], m contiguous
// BMODE 1: B stored [k][n], n contiguous.  BMODE 0: B stored [n][k], k contiguous
// EPI 1: out = relu(acc*inv[m] + (b - m*inv)[m]);  EPI 0: raw store
// Block tile 128x128, BK=16. 8 warps, each computes 64x32 (4x4 tiles of m16n8k8).
// tf32 2-term split: acc += Ahi*Bhi + Alo*Bhi + Ahi*Blo  (~fp32 precision)
#define BM 128
#define BN 128
#define BKk 16
#define LDP 132   // smem row padding (floats) -> conflict-free tf32 frag loads

template<int AMODE, int BMODE, int EPI, int HASB2>
__global__ __launch_bounds__(256, 1)
void gemm_tc(const float* __restrict__ A,  long sA, int lda,
             const float* __restrict__ Bp, long sB, int ldb,
             const float* __restrict__ B2, long sB2,
             float* __restrict__ Cp, long sC, int ldc,
             const float* __restrict__ vg, const float* __restrict__ vb,
             const float* __restrict__ vm, const float* __restrict__ vv,
             int K)
{
    const int bz = blockIdx.z;
    A  += (long)bz * sA;
    Bp += (long)bz * sB;
    Cp += (long)bz * sC;
    if (HASB2) B2 += (long)bz * sB2;

    const int m0 = blockIdx.y * BM;
    const int n0 = blockIdx.x * BN;

    __shared__ float As[BKk][LDP];
    __shared__ float Bs[BKk][LDP];

    const int tid  = threadIdx.x;
    const int lane = tid & 31;
    const int wid  = tid >> 5;
    const int wm   = (wid & 1) * 64;   // warp M offset in block
    const int wn   = (wid >> 1) * 32;  // warp N offset in block
    const int grp  = lane >> 2;        // 0..7
    const int qid  = lane & 3;         // 0..3

    float acc[4][4][4];
    #pragma unroll
    for (int i = 0; i < 4; i++)
        #pragma unroll
        for (int j = 0; j < 4; j++)
            #pragma unroll
            for (int t = 0; t < 4; t++) acc[i][j][t] = 0.f;

    for (int k0 = 0; k0 < K; k0 += BKk) {
        // ---- load A tile (As[k][m]) ----
        if (AMODE == 0) {
            int r = tid >> 2;             // 0..63
            int c = (tid & 3) * 4;        // 0,4,8,12
            #pragma unroll
            for (int it = 0; it < 2; it++) {
                int m = r + it * 64;
                float4 a = *(const float4*)&A[(long)(m0 + m) * lda + k0 + c];
                As[c + 0][m] = a.x; As[c + 1][m] = a.y;
                As[c + 2][m] = a.z; As[c + 3][m] = a.w;
            }
        } else {
            int kk = tid >> 5;            // 0..7
            int mi = (tid & 31) * 4;      // 0..124
            #pragma unroll
            for (int it = 0; it < 2; it++) {
                int k = kk + it * 8;
                *(float4*)&As[k][mi] =
                    *(const float4*)&A[(long)(k0 + k) * lda + m0 + mi];
            }
        }
        // ---- load B tile (Bs[k][n]) ----
        if (BMODE == 1) {
            int kk = tid >> 5;
            int ni = (tid & 31) * 4;
            #pragma unroll
            for (int it = 0; it < 2; it++) {
                int k = kk + it * 8;
                float4 v4 = *(const float4*)&Bp[(long)(k0 + k) * ldb + n0 + ni];
                if (HASB2) {
                    float4 w4 = *(const float4*)&B2[(long)(k0 + k) * ldb + n0 + ni];
                    v4.x += w4.x; v4.y += w4.y; v4.z += w4.z; v4.w += w4.w;
                }
                *(float4*)&Bs[k][ni] = v4;
            }
        } else {
            int r = tid >> 2;
            int c = (tid & 3) * 4;
            #pragma unroll
            for (int it = 0; it < 2; it++) {
                int n = r + it * 64;
                float4 v4 = *(const float4*)&Bp[(long)(n0 + n) * ldb + k0 + c];
                Bs[c + 0][n] = v4.x; Bs[c + 1][n] = v4.y;
                Bs[c + 2][n] = v4.z; Bs[c + 3][n] = v4.w;
            }
        }
        __syncthreads();

        // ---- tensor-core compute: 2 k-steps of 8 ----
        #pragma unroll
        for (int ks = 0; ks < 2; ks++) {
            const int kb = ks * 8;
            // A fragments (4 M-tiles), split hi/lo
            uint32_t ah[4][4], al[4][4];
            #pragma unroll
            for (int mi = 0; mi < 4; mi++) {
                const int r = wm + mi * 16 + grp;
                float x0 = As[kb + qid][r];
                float x1 = As[kb + qid][r + 8];
                float x2 = As[kb + qid + 4][r];
                float x3 = As[kb + qid + 4][r + 8];
                tf32_split(x0, ah[mi][0], al[mi][0]);
                tf32_split(x1, ah[mi][1], al[mi][1]);
                tf32_split(x2, ah[mi][2], al[mi][2]);
                tf32_split(x3, ah[mi][3], al[mi][3]);
            }
            // B fragments (4 N-tiles), split hi/lo
            uint32_t bh[4][2], bl[4][2];
            #pragma unroll
            for (int nj = 0; nj < 4; nj++) {
                const int c = wn + nj * 8 + grp;
                float y0 = Bs[kb + qid][c];
                float y1 = Bs[kb + qid + 4][c];
                tf32_split(y0, bh[nj][0], bl[nj][0]);
                tf32_split(y1, bh[nj][1], bl[nj][1]);
            }
            // mma: hi*hi + lo*hi + hi*lo
            #pragma unroll
            for (int mi = 0; mi < 4; mi++)
                #pragma unroll
                for (int nj = 0; nj < 4; nj++) {
                    mma8(acc[mi][nj], ah[mi][0], ah[mi][1], ah[mi][2], ah[mi][3],
                         bh[nj][0], bh[nj][1]);
                    mma8(acc[mi][nj], al[mi][0], al[mi][1], al[mi][2], al[mi][3],
                         bh[nj][0], bh[nj][1]);
                    mma8(acc[mi][nj], ah[mi][0], ah[mi][1], ah[mi][2], ah[mi][3],
                         bl[nj][0], bl[nj][1]);
                }
        }
        __syncthreads();
    }

    // ---- epilogue ----
    #pragma unroll
    for (int mi = 0; mi < 4; mi++) {
        const int r0 = m0 + wm + mi * 16 + grp;
        const int r1 = r0 + 8;
        float inv0 = 0.f, bet0 = 0.f, inv1 = 0.f, bet1 = 0.f;
        if (EPI == 1) {
            inv0 = vg[r0] * rsqrtf(vv[r0] + EPSF);
            bet0 = vb[r0] - vm[r0] * inv0;
            inv1 = vg[r1] * rsqrtf(vv[r1] + EPSF);
            bet1 = vb[r1] - vm[r1] * inv1;
        }
        #pragma unroll
        for (int nj = 0; nj < 4; nj++) {
            const int c = n0 + wn + nj * 8 + qid * 2;
            float2 o0, o1;
            if (EPI == 1) {
                o0.x = fmaxf(fmaf(acc[mi][nj][0], inv0, bet0), 0.f);
                o0.y = fmaxf(fmaf(acc[mi][nj][1], inv0, bet0), 0.f);
                o1.x = fmaxf(fmaf(acc[mi][nj][2], inv1, bet1), 0.f);
                o1.y = fmaxf(fmaf(acc[mi][nj][3], inv1, bet1), 0.f);
            } else {
                o0.x = acc[mi][nj][0]; o0.y = acc[mi][nj][1];
                o1.x = acc[mi][nj][2]; o1.y = acc[mi][nj][3];
            }
            *(float2*)&Cp[(long)r0 * ldc + c] = o0;
            *(float2*)&Cp[(long)r1 * ldc + c] = o1;
        }
    }
}

// ---------------- row softmax (rows of 4096) ----------------------------------
__global__ void softmax_k(float* __restrict__ S)
{
    const long row = blockIdx.x;
    float4* p = (float4*)(S + row * 4096);
    const int tid = threadIdx.x;   // 256 threads, 16 elements each

    float4 v[4];
    float mx = -3.4e38f;
    #pragma unroll
    for (int i = 0; i < 4; i++) {
        v[i] = p[tid + 256 * i];
        mx = fmaxf(mx, fmaxf(fmaxf(v[i].x, v[i].y), fmaxf(v[i].z, v[i].w)));
    }

    __shared__ float red[256];
    red[tid] = mx; __syncthreads();
    #pragma unroll
    for (int s = 128; s > 0; s >>= 1) {
        if (tid < s) red[tid] = fmaxf(red[tid], red[tid + s]);
        __syncthreads();
    }
    mx = red[0];
    __syncthreads();

    float sum = 0.f;
    #pragma unroll
    for (int i = 0; i < 4; i++) {
        v[i].x = __expf(v[i].x - mx); v[i].y = __expf(v[i].y - mx);
        v[i].z = __expf(v[i].z - mx); v[i].w = __expf(v[i].w - mx);
        sum += v[i].x + v[i].y + v[i].z + v[i].w;
    }
    red[tid] = sum; __syncthreads();
    #pragma unroll
    for (int s = 128; s > 0; s >>= 1) {
        if (tid < s) red[tid] += red[tid + s];
        __syncthreads();
    }
    const float r = 1.f / red[0];
    #pragma unroll
    for (int i = 0; i < 4; i++) {
        v[i].x *= r; v[i].y *= r; v[i].z *= r; v[i].w *= r;
        p[tid + 256 * i] = v[i];
    }
}

// ---------------- launch --------------------------------------------------------
extern "C" void kernel_launch(void* const* d_in, const int* in_sizes, int n_in,
                              void* d_out, int out_size)
{
    const float* feature = (const float*)d_in[0];
    const float* rW = (const float*)d_in[1];
    const float* rg = (const float*)d_in[2];
    const float* rb = (const float*)d_in[3];
    const float* rm = (const float*)d_in[4];
    const float* rv = (const float*)d_in[5];
    const float* qW = (const float*)d_in[6];
    const float* qg = (const float*)d_in[7];
    const float* qb = (const float*)d_in[8];
    const float* qm = (const float*)d_in[9];
    const float* qv = (const float*)d_in[10];
    const float* kW = (const float*)d_in[11];
    const float* kg = (const float*)d_in[12];
    const float* kb = (const float*)d_in[13];
    const float* km = (const float*)d_in[14];
    const float* kv = (const float*)d_in[15];
    const float* vW = (const float*)d_in[16];
    const float* vg = (const float*)d_in[17];
    const float* vb = (const float*)d_in[18];
    const float* vm = (const float*)d_in[19];
    const float* vvp = (const float*)d_in[20];
    const float* uW = (const float*)d_in[21];
    const float* ug = (const float*)d_in[22];
    const float* ub = (const float*)d_in[23];
    const float* um = (const float*)d_in[24];
    const float* uv = (const float*)d_in[25];

    float *f, *q, *k, *v, *attn, *upd;
    cudaGetSymbolAddress((void**)&f,    g_f);
    cudaGetSymbolAddress((void**)&q,    g_q);
    cudaGetSymbolAddress((void**)&k,    g_kk);
    cudaGetSymbolAddress((void**)&v,    g_v);
    cudaGetSymbolAddress((void**)&attn, g_attn);
    cudaGetSymbolAddress((void**)&upd,  g_upd);

    const long sF = 512L * 4096;          // per-batch stride of f/q/k/v/upd
    const long sX = 2048L * 4096;         // per-batch stride of feature / out
    const long sS = 4096L * 4096;         // per-batch stride of attn
    dim3 blk(256);

    // 1) f = relu(bn(rW @ feature))            M=512 N=4096 K=2048
    gemm_tc<0,1,1,0><<<dim3(32,4,4), blk>>>(rW, 0, 2048,
                                            feature, sX, 4096,
                                            nullptr, 0,
                                            f, sF, 4096,
                                            rg, rb, rm, rv, 2048);
    // 2) q,k,v from f                          M=512 N=4096 K=512
    gemm_tc<0,1,1,0><<<dim3(32,4,4), blk>>>(qW, 0, 512, f, sF, 4096, nullptr, 0,
                                            q, sF, 4096, qg, qb, qm, qv, 512);
    gemm_tc<0,1,1,0><<<dim3(32,4,4), blk>>>(kW, 0, 512, f, sF, 4096, nullptr, 0,
                                            k, sF, 4096, kg, kb, km, kv, 512);
    gemm_tc<0,1,1,0><<<dim3(32,4,4), blk>>>(vW, 0, 512, f, sF, 4096, nullptr, 0,
                                            v, sF, 4096, vg, vb, vm, vvp, 512);
    // 3) S[n][m] = sum_c q[c][n] k[c][m]       M=4096 N=4096 K=512
    gemm_tc<1,1,0,0><<<dim3(32,32,4), blk>>>(q, sF, 4096,
                                             k, sF, 4096,
                                             nullptr, 0,
                                             attn, sS, 4096,
                                             nullptr, nullptr, nullptr, nullptr, 512);
    // 4) softmax rows
    softmax_k<<<4 * 4096, 256>>>(attn);
    // 5) upd[c][n] = sum_m v[c][m] attn[n][m]  M=512 N=4096 K=4096
    gemm_tc<0,0,0,0><<<dim3(32,4,4), blk>>>(v, sF, 4096,
                                            attn, sS, 4096,
                                            nullptr, 0,
                                            upd, sF, 4096,
                                            nullptr, nullptr, nullptr, nullptr, 4096);
    // 6) out = relu(bn(uW @ (f + upd)))        M=2048 N=4096 K=512
    gemm_tc<0,1,1,1><<<dim3(32,16,4), blk>>>(uW, 0, 512,
                                             f, sF, 4096,
                                             upd, sF,
                                             (float*)d_out, sX, 4096,
                                             ug, ub, um, uv, 512);
}

// round 10
// speedup vs baseline: 1.3417x; 1.3417x over previous
#include <cuda_runtime.h>
#include <cstdint>

#define EPSF 1e-5f

// ---------------- scratch (device globals; no allocation allowed) -------------
// B=4, C=2048, R=512, H=W=64, N=4096
__device__ float g_f   [4L*512*4096];     // 32 MB
__device__ float g_q   [4L*512*4096];
__device__ float g_kk  [4L*512*4096];
__device__ float g_v   [4L*512*4096];
__device__ float g_upd [4L*512*4096];
__device__ float g_attn[4L*4096*4096];    // 268 MB

// ---------------- tf32 helpers -------------------------------------------------
__device__ __forceinline__ uint32_t f2tf32(float x) {
    uint32_t r;
    asm("cvt.rna.tf32.f32 %0, %1;" : "=r"(r) : "f"(x));
    return r;
}
// split x into tf32 hi + tf32 lo (x ~= hi + lo to ~22 mantissa bits)
__device__ __forceinline__ void tf32_split(float x, uint32_t& hi, uint32_t& lo) {
    hi = f2tf32(x);
    lo = f2tf32(x - __uint_as_float(hi));
}

__device__ __forceinline__ void mma8(float* c,
                                     uint32_t a0, uint32_t a1, uint32_t a2, uint32_t a3,
                                     uint32_t b0, uint32_t b1) {
    asm volatile(
        "mma.sync.aligned.m16n8k8.row.col.f32.tf32.tf32.f32 "
        "{%0,%1,%2,%3}, {%4,%5,%6,%7}, {%8,%9}, {%0,%1,%2,%3};"
        : "+f"(c[0]), "+f"(c[1]), "+f"(c[2]), "+f"(c[3])
        : "r"(a0), "r"(a1), "r"(a2), "r"(a3), "r"(b0), "r"(b1));
}

// ---------------- tensor-core GEMM ---------------------------------------------
// C[m][n] = sum_k A(m,k) * B(k,n)   (+ optional B2 fused add, + optional BN+ReLU)
// AMODE 0: A stored [m][k], k contiguous.  AMODE 1: A stored [k][m], m contiguous
// BMODE 1: B stored [k][n], n contiguous.  BMODE 0: B stored [n][k], k contiguous
// EPI 1: out = relu(acc*inv[m] + (b - m*inv)[m]);  EPI 0: raw store
// SPLIT 1: tf32 2-term split (acc += Ahi*Bhi + Alo*Bhi + Ahi*Blo, ~fp32 precision)
// SPLIT 0: plain tf32 single MMA (used post-softmax where error can't amplify)
// Block tile 128x128, BK=16. 8 warps, each computes 64x32 (4x4 tiles of m16n8k8).
#define BM 128
#define BN 128
#define BKk 16
#define LDP 132   // smem row padding (floats) -> conflict-free tf32 frag loads

template<int AMODE, int BMODE, int EPI, int HASB2, int SPLIT>
__global__ __launch_bounds__(256, 1)
void gemm_tc(const float* __restrict__ A,  long sA, int lda,
             const float* __restrict__ Bp, long sB, int ldb,
             const float* __restrict__ B2, long sB2,
             float* __restrict__ Cp, long sC, int ldc,
             const float* __restrict__ vg, const float* __restrict__ vb,
             const float* __restrict__ vm, const float* __restrict__ vv,
             int K)
{
    const int bz = blockIdx.z;
    A  += (long)bz * sA;
    Bp += (long)bz * sB;
    Cp += (long)bz * sC;
    if (HASB2) B2 += (long)bz * sB2;

    const int m0 = blockIdx.y * BM;
    const int n0 = blockIdx.x * BN;

    __shared__ float As[BKk][LDP];
    __shared__ float Bs[BKk][LDP];

    const int tid  = threadIdx.x;
    const int lane = tid & 31;
    const int wid  = tid >> 5;
    const int wm   = (wid & 1) * 64;   // warp M offset in block
    const int wn   = (wid >> 1) * 32;  // warp N offset in block
    const int grp  = lane >> 2;        // 0..7
    const int qid  = lane & 3;         // 0..3

    float acc[4][4][4];
    #pragma unroll
    for (int i = 0; i < 4; i++)
        #pragma unroll
        for (int j = 0; j < 4; j++)
            #pragma unroll
            for (int t = 0; t < 4; t++) acc[i][j][t] = 0.f;

    for (int k0 = 0; k0 < K; k0 += BKk) {
        // ---- load A tile (As[k][m]) ----
        if (AMODE == 0) {
            int r = tid >> 2;             // 0..63
            int c = (tid & 3) * 4;        // 0,4,8,12
            #pragma unroll
            for (int it = 0; it < 2; it++) {
                int m = r + it * 64;
                float4 a = *(const float4*)&A[(long)(m0 + m) * lda + k0 + c];
                As[c + 0][m] = a.x; As[c + 1][m] = a.y;
                As[c + 2][m] = a.z; As[c + 3][m] = a.w;
            }
        } else {
            int kk = tid >> 5;            // 0..7
            int mi = (tid & 31) * 4;      // 0..124
            #pragma unroll
            for (int it = 0; it < 2; it++) {
                int k = kk + it * 8;
                *(float4*)&As[k][mi] =
                    *(const float4*)&A[(long)(k0 + k) * lda + m0 + mi];
            }
        }
        // ---- load B tile (Bs[k][n]) ----
        if (BMODE == 1) {
            int kk = tid >> 5;
            int ni = (tid & 31) * 4;
            #pragma unroll
            for (int it = 0; it < 2; it++) {
                int k = kk + it * 8;
                float4 v4 = *(const float4*)&Bp[(long)(k0 + k) * ldb + n0 + ni];
                if (HASB2) {
                    float4 w4 = *(const float4*)&B2[(long)(k0 + k) * ldb + n0 + ni];
                    v4.x += w4.x; v4.y += w4.y; v4.z += w4.z; v4.w += w4.w;
                }
                *(float4*)&Bs[k][ni] = v4;
            }
        } else {
            int r = tid >> 2;
            int c = (tid & 3) * 4;
            #pragma unroll
            for (int it = 0; it < 2; it++) {
                int n = r + it * 64;
                float4 v4 = *(const float4*)&Bp[(long)(n0 + n) * ldb + k0 + c];
                Bs[c + 0][n] = v4.x; Bs[c + 1][n] = v4.y;
                Bs[c + 2][n] = v4.z; Bs[c + 3][n] = v4.w;
            }
        }
        __syncthreads();

        // ---- tensor-core compute: 2 k-steps of 8 ----
        #pragma unroll
        for (int ks = 0; ks < 2; ks++) {
            const int kb = ks * 8;
            // A fragments (4 M-tiles)
            uint32_t ah[4][4], al[4][4];
            #pragma unroll
            for (int mi = 0; mi < 4; mi++) {
                const int r = wm + mi * 16 + grp;
                float x0 = As[kb + qid][r];
                float x1 = As[kb + qid][r + 8];
                float x2 = As[kb + qid + 4][r];
                float x3 = As[kb + qid + 4][r + 8];
                if (SPLIT) {
                    tf32_split(x0, ah[mi][0], al[mi][0]);
                    tf32_split(x1, ah[mi][1], al[mi][1]);
                    tf32_split(x2, ah[mi][2], al[mi][2]);
                    tf32_split(x3, ah[mi][3], al[mi][3]);
                } else {
                    ah[mi][0] = f2tf32(x0); ah[mi][1] = f2tf32(x1);
                    ah[mi][2] = f2tf32(x2); ah[mi][3] = f2tf32(x3);
                }
            }
            // B fragments (4 N-tiles)
            uint32_t bh[4][2], bl[4][2];
            #pragma unroll
            for (int nj = 0; nj < 4; nj++) {
                const int c = wn + nj * 8 + grp;
                float y0 = Bs[kb + qid][c];
                float y1 = Bs[kb + qid + 4][c];
                if (SPLIT) {
                    tf32_split(y0, bh[nj][0], bl[nj][0]);
                    tf32_split(y1, bh[nj][1], bl[nj][1]);
                } else {
                    bh[nj][0] = f2tf32(y0);
                    bh[nj][1] = f2tf32(y1);
                }
            }
            // mma: hi*hi (+ lo*hi + hi*lo when SPLIT)
            #pragma unroll
            for (int mi = 0; mi < 4; mi++)
                #pragma unroll
                for (int nj = 0; nj < 4; nj++) {
                    mma8(acc[mi][nj], ah[mi][0], ah[mi][1], ah[mi][2], ah[mi][3],
                         bh[nj][0], bh[nj][1]);
                    if (SPLIT) {
                        mma8(acc[mi][nj], al[mi][0], al[mi][1], al[mi][2], al[mi][3],
                             bh[nj][0], bh[nj][1]);
                        mma8(acc[mi][nj], ah[mi][0], ah[mi][1], ah[mi][2], ah[mi][3],
                             bl[nj][0], bl[nj][1]);
                    }
                }
        }
        __syncthreads();
    }

    // ---- epilogue ----
    #pragma unroll
    for (int mi = 0; mi < 4; mi++) {
        const int r0 = m0 + wm + mi * 16 + grp;
        const int r1 = r0 + 8;
        float inv0 = 0.f, bet0 = 0.f, inv1 = 0.f, bet1 = 0.f;
        if (EPI == 1) {
            inv0 = vg[r0] * rsqrtf(vv[r0] + EPSF);
            bet0 = vb[r0] - vm[r0] * inv0;
            inv1 = vg[r1] * rsqrtf(vv[r1] + EPSF);
            bet1 = vb[r1] - vm[r1] * inv1;
        }
        #pragma unroll
        for (int nj = 0; nj < 4; nj++) {
            const int c = n0 + wn + nj * 8 + qid * 2;
            float2 o0, o1;
            if (EPI == 1) {
                o0.x = fmaxf(fmaf(acc[mi][nj][0], inv0, bet0), 0.f);
                o0.y = fmaxf(fmaf(acc[mi][nj][1], inv0, bet0), 0.f);
                o1.x = fmaxf(fmaf(acc[mi][nj][2], inv1, bet1), 0.f);
                o1.y = fmaxf(fmaf(acc[mi][nj][3], inv1, bet1), 0.f);
            } else {
                o0.x = acc[mi][nj][0]; o0.y = acc[mi][nj][1];
                o1.x = acc[mi][nj][2]; o1.y = acc[mi][nj][3];
            }
            *(float2*)&Cp[(long)r0 * ldc + c] = o0;
            *(float2*)&Cp[(long)r1 * ldc + c] = o1;
        }
    }
}

// ---------------- row softmax (rows of 4096) ----------------------------------
__global__ void softmax_k(float* __restrict__ S)
{
    const long row = blockIdx.x;
    float4* p = (float4*)(S + row * 4096);
    const int tid = threadIdx.x;   // 256 threads, 16 elements each

    float4 v[4];
    float mx = -3.4e38f;
    #pragma unroll
    for (int i = 0; i < 4; i++) {
        v[i] = p[tid + 256 * i];
        mx = fmaxf(mx, fmaxf(fmaxf(v[i].x, v[i].y), fmaxf(v[i].z, v[i].w)));
    }

    __shared__ float red[256];
    red[tid] = mx; __syncthreads();
    #pragma unroll
    for (int s = 128; s > 0; s >>= 1) {
        if (tid < s) red[tid] = fmaxf(red[tid], red[tid + s]);
        __syncthreads();
    }
    mx = red[0];
    __syncthreads();

    float sum = 0.f;
    #pragma unroll
    for (int i = 0; i < 4; i++) {
        v[i].x = __expf(v[i].x - mx); v[i].y = __expf(v[i].y - mx);
        v[i].z = __expf(v[i].z - mx); v[i].w = __expf(v[i].w - mx);
        sum += v[i].x + v[i].y + v[i].z + v[i].w;
    }
    red[tid] = sum; __syncthreads();
    #pragma unroll
    for (int s = 128; s > 0; s >>= 1) {
        if (tid < s) red[tid] += red[tid + s];
        __syncthreads();
    }
    const float r = 1.f / red[0];
    #pragma unroll
    for (int i = 0; i < 4; i++) {
        v[i].x *= r; v[i].y *= r; v[i].z *= r; v[i].w *= r;
        p[tid + 256 * i] = v[i];
    }
}

// ---------------- launch --------------------------------------------------------
extern "C" void kernel_launch(void* const* d_in, const int* in_sizes, int n_in,
                              void* d_out, int out_size)
{
    const float* feature = (const float*)d_in[0];
    const float* rW = (const float*)d_in[1];
    const float* rg = (const float*)d_in[2];
    const float* rb = (const float*)d_in[3];
    const float* rm = (const float*)d_in[4];
    const float* rv = (const float*)d_in[5];
    const float* qW = (const float*)d_in[6];
    const float* qg = (const float*)d_in[7];
    const float* qb = (const float*)d_in[8];
    const float* qm = (const float*)d_in[9];
    const float* qv = (const float*)d_in[10];
    const float* kW = (const float*)d_in[11];
    const float* kg = (const float*)d_in[12];
    const float* kb = (const float*)d_in[13];
    const float* km = (const float*)d_in[14];
    const float* kv = (const float*)d_in[15];
    const float* vW = (const float*)d_in[16];
    const float* vg = (const float*)d_in[17];
    const float* vb = (const float*)d_in[18];
    const float* vm = (const float*)d_in[19];
    const float* vvp = (const float*)d_in[20];
    const float* uW = (const float*)d_in[21];
    const float* ug = (const float*)d_in[22];
    const float* ub = (const float*)d_in[23];
    const float* um = (const float*)d_in[24];
    const float* uv = (const float*)d_in[25];

    float *f, *q, *k, *v, *attn, *upd;
    cudaGetSymbolAddress((void**)&f,    g_f);
    cudaGetSymbolAddress((void**)&q,    g_q);
    cudaGetSymbolAddress((void**)&k,    g_kk);
    cudaGetSymbolAddress((void**)&v,    g_v);
    cudaGetSymbolAddress((void**)&attn, g_attn);
    cudaGetSymbolAddress((void**)&upd,  g_upd);

    const long sF = 512L * 4096;          // per-batch stride of f/q/k/v/upd
    const long sX = 2048L * 4096;         // per-batch stride of feature / out
    const long sS = 4096L * 4096;         // per-batch stride of attn
    dim3 blk(256);

    // 1) f = relu(bn(rW @ feature))            M=512 N=4096 K=2048   [split]
    gemm_tc<0,1,1,0,1><<<dim3(32,4,4), blk>>>(rW, 0, 2048,
                                              feature, sX, 4096,
                                              nullptr, 0,
                                              f, sF, 4096,
                                              rg, rb, rm, rv, 2048);
    // 2) q,k,v from f                          M=512 N=4096 K=512    [split]
    gemm_tc<0,1,1,0,1><<<dim3(32,4,4), blk>>>(qW, 0, 512, f, sF, 4096, nullptr, 0,
                                              q, sF, 4096, qg, qb, qm, qv, 512);
    gemm_tc<0,1,1,0,1><<<dim3(32,4,4), blk>>>(kW, 0, 512, f, sF, 4096, nullptr, 0,
                                              k, sF, 4096, kg, kb, km, kv, 512);
    gemm_tc<0,1,1,0,1><<<dim3(32,4,4), blk>>>(vW, 0, 512, f, sF, 4096, nullptr, 0,
                                              v, sF, 4096, vg, vb, vm, vvp, 512);
    // 3) S[n][m] = sum_c q[c][n] k[c][m]       M=4096 N=4096 K=512   [split]
    gemm_tc<1,1,0,0,1><<<dim3(32,32,4), blk>>>(q, sF, 4096,
                                               k, sF, 4096,
                                               nullptr, 0,
                                               attn, sS, 4096,
                                               nullptr, nullptr, nullptr, nullptr, 512);
    // 4) softmax rows
    softmax_k<<<4 * 4096, 256>>>(attn);
    // 5) upd[c][n] = sum_m v[c][m] attn[n][m]  M=512 N=4096 K=4096   [plain tf32]
    gemm_tc<0,0,0,0,0><<<dim3(32,4,4), blk>>>(v, sF, 4096,
                                              attn, sS, 4096,
                                              nullptr, 0,
                                              upd, sF, 4096,
                                              nullptr, nullptr, nullptr, nullptr, 4096);
    // 6) out = relu(bn(uW @ (f + upd)))        M=2048 N=4096 K=512   [plain tf32]
    gemm_tc<0,1,1,1,0><<<dim3(32,16,4), blk>>>(uW, 0, 512,
                                               f, sF, 4096,
                                               upd, sF,
                                               (float*)d_out, sX, 4096,
                                               ug, ub, um, uv, 512);
}

// round 15
// speedup vs baseline: 1.5528x; 1.1573x over previous
#include <cuda_runtime.h>
#include <cstdint>

#define EPSF 1e-5f

// ---------------- scratch (device globals; no allocation allowed) -------------
// B=4, C=2048, R=512, H=W=64, N=4096
__device__ float g_f   [4L*512*4096];     // 32 MB
__device__ float g_q   [4L*512*4096];
__device__ float g_kk  [4L*512*4096];
__device__ float g_v   [4L*512*4096];
__device__ float g_upd [4L*512*4096];
__device__ float g_attn[4L*4096*4096];    // 268 MB

// ---------------- tf32 helpers -------------------------------------------------
__device__ __forceinline__ uint32_t f2tf32(float x) {
    uint32_t r;
    asm("cvt.rna.tf32.f32 %0, %1;" : "=r"(r) : "f"(x));
    return r;
}
// split x into tf32 hi + tf32 lo (x ~= hi + lo to ~22 mantissa bits)
__device__ __forceinline__ void tf32_split(float x, uint32_t& hi, uint32_t& lo) {
    hi = f2tf32(x);
    lo = f2tf32(x - __uint_as_float(hi));
}

__device__ __forceinline__ void mma8(float* c,
                                     uint32_t a0, uint32_t a1, uint32_t a2, uint32_t a3,
                                     uint32_t b0, uint32_t b1) {
    asm volatile(
        "mma.sync.aligned.m16n8k8.row.col.f32.tf32.tf32.f32 "
        "{%0,%1,%2,%3}, {%4,%5,%6,%7}, {%8,%9}, {%0,%1,%2,%3};"
        : "+f"(c[0]), "+f"(c[1]), "+f"(c[2]), "+f"(c[3])
        : "r"(a0), "r"(a1), "r"(a2), "r"(a3), "r"(b0), "r"(b1));
}

// ---------------- tensor-core GEMM ---------------------------------------------
// C[m][n] = sum_k A(m,k) * B(k,n)   (+ optional B2 fused add, + optional BN+ReLU)
// AMODE 0: A stored [m][k], k contiguous.  AMODE 1: A stored [k][m], m contiguous
// BMODE 1: B stored [k][n], n contiguous.  BMODE 0: B stored [n][k], k contiguous
// EPI 1: out = relu(acc*inv[m] + (b - m*inv)[m]);  EPI 0: raw store
// SPLIT 1: tf32 2-term split (acc += Ahi*Bhi + Alo*Bhi + Ahi*Blo, ~fp32 precision)
// SPLIT 0: plain tf32 single MMA (post-softmax GEMMs, where error can't amplify)
// Elements are split/converted ONCE at tile-load time into smem (tf32 bit
// patterns); the mainloop is pure LDS + MMA.
// Block tile 128x128, BK=16. 8 warps, each computes 64x32 (4x4 tiles of m16n8k8).
#define BM 128
#define BN 128
#define BKk 16
#define LDP 132   // smem row padding (words) -> conflict-free frag loads

template<int AMODE, int BMODE, int EPI, int HASB2, int SPLIT>
__global__ __launch_bounds__(256, 2)
void gemm_tc(const float* __restrict__ A,  long sA, int lda,
             const float* __restrict__ Bp, long sB, int ldb,
             const float* __restrict__ B2, long sB2,
             float* __restrict__ Cp, long sC, int ldc,
             const float* __restrict__ vg, const float* __restrict__ vb,
             const float* __restrict__ vm, const float* __restrict__ vv,
             int K)
{
    const int bz = blockIdx.z;
    A  += (long)bz * sA;
    Bp += (long)bz * sB;
    Cp += (long)bz * sC;
    if (HASB2) B2 += (long)bz * sB2;

    const int m0 = blockIdx.y * BM;
    const int n0 = blockIdx.x * BN;

    __shared__ uint32_t AsH[BKk][LDP];
    __shared__ uint32_t BsH[BKk][LDP];
    __shared__ uint32_t AsL[SPLIT ? BKk : 1][LDP];
    __shared__ uint32_t BsL[SPLIT ? BKk : 1][LDP];

    const int tid  = threadIdx.x;
    const int lane = tid & 31;
    const int wid  = tid >> 5;
    const int wm   = (wid & 1) * 64;   // warp M offset in block
    const int wn   = (wid >> 1) * 32;  // warp N offset in block
    const int grp  = lane >> 2;        // 0..7
    const int qid  = lane & 3;         // 0..3

    float acc[4][4][4];
    #pragma unroll
    for (int i = 0; i < 4; i++)
        #pragma unroll
        for (int j = 0; j < 4; j++)
            #pragma unroll
            for (int t = 0; t < 4; t++) acc[i][j][t] = 0.f;

    for (int k0 = 0; k0 < K; k0 += BKk) {
        // ---- load + convert A tile ----
        if (AMODE == 0) {
            int r = tid >> 2;             // 0..63
            int c = (tid & 3) * 4;        // 0,4,8,12
            #pragma unroll
            for (int it = 0; it < 2; it++) {
                int m = r + it * 64;
                float4 a = *(const float4*)&A[(long)(m0 + m) * lda + k0 + c];
                if (SPLIT) {
                    uint32_t h, l;
                    tf32_split(a.x, h, l); AsH[c + 0][m] = h; AsL[c + 0][m] = l;
                    tf32_split(a.y, h, l); AsH[c + 1][m] = h; AsL[c + 1][m] = l;
                    tf32_split(a.z, h, l); AsH[c + 2][m] = h; AsL[c + 2][m] = l;
                    tf32_split(a.w, h, l); AsH[c + 3][m] = h; AsL[c + 3][m] = l;
                } else {
                    AsH[c + 0][m] = f2tf32(a.x); AsH[c + 1][m] = f2tf32(a.y);
                    AsH[c + 2][m] = f2tf32(a.z); AsH[c + 3][m] = f2tf32(a.w);
                }
            }
        } else {
            int kk = tid >> 5;            // 0..7
            int mi = (tid & 31) * 4;      // 0..124
            #pragma unroll
            for (int it = 0; it < 2; it++) {
                int k = kk + it * 8;
                float4 a = *(const float4*)&A[(long)(k0 + k) * lda + m0 + mi];
                if (SPLIT) {
                    uint4 h4, l4;
                    tf32_split(a.x, h4.x, l4.x);
                    tf32_split(a.y, h4.y, l4.y);
                    tf32_split(a.z, h4.z, l4.z);
                    tf32_split(a.w, h4.w, l4.w);
                    *(uint4*)&AsH[k][mi] = h4;
                    *(uint4*)&AsL[k][mi] = l4;
                } else {
                    uint4 h4;
                    h4.x = f2tf32(a.x); h4.y = f2tf32(a.y);
                    h4.z = f2tf32(a.z); h4.w = f2tf32(a.w);
                    *(uint4*)&AsH[k][mi] = h4;
                }
            }
        }
        // ---- load + convert B tile ----
        if (BMODE == 1) {
            int kk = tid >> 5;
            int ni = (tid & 31) * 4;
            #pragma unroll
            for (int it = 0; it < 2; it++) {
                int k = kk + it * 8;
                float4 v4 = *(const float4*)&Bp[(long)(k0 + k) * ldb + n0 + ni];
                if (HASB2) {
                    float4 w4 = *(const float4*)&B2[(long)(k0 + k) * ldb + n0 + ni];
                    v4.x += w4.x; v4.y += w4.y; v4.z += w4.z; v4.w += w4.w;
                }
                if (SPLIT) {
                    uint4 h4, l4;
                    tf32_split(v4.x, h4.x, l4.x);
                    tf32_split(v4.y, h4.y, l4.y);
                    tf32_split(v4.z, h4.z, l4.z);
                    tf32_split(v4.w, h4.w, l4.w);
                    *(uint4*)&BsH[k][ni] = h4;
                    *(uint4*)&BsL[k][ni] = l4;
                } else {
                    uint4 h4;
                    h4.x = f2tf32(v4.x); h4.y = f2tf32(v4.y);
                    h4.z = f2tf32(v4.z); h4.w = f2tf32(v4.w);
                    *(uint4*)&BsH[k][ni] = h4;
                }
            }
        } else {
            int r = tid >> 2;
            int c = (tid & 3) * 4;
            #pragma unroll
            for (int it = 0; it < 2; it++) {
                int n = r + it * 64;
                float4 v4 = *(const float4*)&Bp[(long)(n0 + n) * ldb + k0 + c];
                if (SPLIT) {
                    uint32_t h, l;
                    tf32_split(v4.x, h, l); BsH[c + 0][n] = h; BsL[c + 0][n] = l;
                    tf32_split(v4.y, h, l); BsH[c + 1][n] = h; BsL[c + 1][n] = l;
                    tf32_split(v4.z, h, l); BsH[c + 2][n] = h; BsL[c + 2][n] = l;
                    tf32_split(v4.w, h, l); BsH[c + 3][n] = h; BsL[c + 3][n] = l;
                } else {
                    BsH[c + 0][n] = f2tf32(v4.x); BsH[c + 1][n] = f2tf32(v4.y);
                    BsH[c + 2][n] = f2tf32(v4.z); BsH[c + 3][n] = f2tf32(v4.w);
                }
            }
        }
        __syncthreads();

        // ---- tensor-core compute: 2 k-steps of 8, pure LDS + MMA ----
        #pragma unroll
        for (int ks = 0; ks < 2; ks++) {
            const int kb = ks * 8;
            // hi fragments
            uint32_t ah[4][4];
            #pragma unroll
            for (int mi = 0; mi < 4; mi++) {
                const int r = wm + mi * 16 + grp;
                ah[mi][0] = AsH[kb + qid][r];
                ah[mi][1] = AsH[kb + qid][r + 8];
                ah[mi][2] = AsH[kb + qid + 4][r];
                ah[mi][3] = AsH[kb + qid + 4][r + 8];
            }
            uint32_t bh[4][2];
            #pragma unroll
            for (int nj = 0; nj < 4; nj++) {
                const int c = wn + nj * 8 + grp;
                bh[nj][0] = BsH[kb + qid][c];
                bh[nj][1] = BsH[kb + qid + 4][c];
            }
            // hi*hi
            #pragma unroll
            for (int mi = 0; mi < 4; mi++)
                #pragma unroll
                for (int nj = 0; nj < 4; nj++)
                    mma8(acc[mi][nj], ah[mi][0], ah[mi][1], ah[mi][2], ah[mi][3],
                         bh[nj][0], bh[nj][1]);
            if (SPLIT) {
                // lo*hi  (A-lo loaded just-in-time, small live range)
                #pragma unroll
                for (int mi = 0; mi < 4; mi++) {
                    const int r = wm + mi * 16 + grp;
                    uint32_t al0 = AsL[kb + qid][r];
                    uint32_t al1 = AsL[kb + qid][r + 8];
                    uint32_t al2 = AsL[kb + qid + 4][r];
                    uint32_t al3 = AsL[kb + qid + 4][r + 8];
                    #pragma unroll
                    for (int nj = 0; nj < 4; nj++)
                        mma8(acc[mi][nj], al0, al1, al2, al3,
                             bh[nj][0], bh[nj][1]);
                }
                // hi*lo  (B-lo loaded just-in-time)
                #pragma unroll
                for (int nj = 0; nj < 4; nj++) {
                    const int c = wn + nj * 8 + grp;
                    uint32_t bl0 = BsL[kb + qid][c];
                    uint32_t bl1 = BsL[kb + qid + 4][c];
                    #pragma unroll
                    for (int mi = 0; mi < 4; mi++)
                        mma8(acc[mi][nj], ah[mi][0], ah[mi][1], ah[mi][2], ah[mi][3],
                             bl0, bl1);
                }
            }
        }
        __syncthreads();
    }

    // ---- epilogue ----
    #pragma unroll
    for (int mi = 0; mi < 4; mi++) {
        const int r0 = m0 + wm + mi * 16 + grp;
        const int r1 = r0 + 8;
        float inv0 = 0.f, bet0 = 0.f, inv1 = 0.f, bet1 = 0.f;
        if (EPI == 1) {
            inv0 = vg[r0] * rsqrtf(vv[r0] + EPSF);
            bet0 = vb[r0] - vm[r0] * inv0;
            inv1 = vg[r1] * rsqrtf(vv[r1] + EPSF);
            bet1 = vb[r1] - vm[r1] * inv1;
        }
        #pragma unroll
        for (int nj = 0; nj < 4; nj++) {
            const int c = n0 + wn + nj * 8 + qid * 2;
            float2 o0, o1;
            if (EPI == 1) {
                o0.x = fmaxf(fmaf(acc[mi][nj][0], inv0, bet0), 0.f);
                o0.y = fmaxf(fmaf(acc[mi][nj][1], inv0, bet0), 0.f);
                o1.x = fmaxf(fmaf(acc[mi][nj][2], inv1, bet1), 0.f);
                o1.y = fmaxf(fmaf(acc[mi][nj][3], inv1, bet1), 0.f);
            } else {
                o0.x = acc[mi][nj][0]; o0.y = acc[mi][nj][1];
                o1.x = acc[mi][nj][2]; o1.y = acc[mi][nj][3];
            }
            *(float2*)&Cp[(long)r0 * ldc + c] = o0;
            *(float2*)&Cp[(long)r1 * ldc + c] = o1;
        }
    }
}

// ---------------- row softmax (rows of 4096) ----------------------------------
__global__ void softmax_k(float* __restrict__ S)
{
    const long row = blockIdx.x;
    float4* p = (float4*)(S + row * 4096);
    const int tid = threadIdx.x;   // 256 threads, 16 elements each

    float4 v[4];
    float mx = -3.4e38f;
    #pragma unroll
    for (int i = 0; i < 4; i++) {
        v[i] = p[tid + 256 * i];
        mx = fmaxf(mx, fmaxf(fmaxf(v[i].x, v[i].y), fmaxf(v[i].z, v[i].w)));
    }

    __shared__ float red[256];
    red[tid] = mx; __syncthreads();
    #pragma unroll
    for (int s = 128; s > 0; s >>= 1) {
        if (tid < s) red[tid] = fmaxf(red[tid], red[tid + s]);
        __syncthreads();
    }
    mx = red[0];
    __syncthreads();

    float sum = 0.f;
    #pragma unroll
    for (int i = 0; i < 4; i++) {
        v[i].x = __expf(v[i].x - mx); v[i].y = __expf(v[i].y - mx);
        v[i].z = __expf(v[i].z - mx); v[i].w = __expf(v[i].w - mx);
        sum += v[i].x + v[i].y + v[i].z + v[i].w;
    }
    red[tid] = sum; __syncthreads();
    #pragma unroll
    for (int s = 128; s > 0; s >>= 1) {
        if (tid < s) red[tid] += red[tid + s];
        __syncthreads();
    }
    const float r = 1.f / red[0];
    #pragma unroll
    for (int i = 0; i < 4; i++) {
        v[i].x *= r; v[i].y *= r; v[i].z *= r; v[i].w *= r;
        p[tid + 256 * i] = v[i];
    }
}

// ---------------- launch --------------------------------------------------------
extern "C" void kernel_launch(void* const* d_in, const int* in_sizes, int n_in,
                              void* d_out, int out_size)
{
    const float* feature = (const float*)d_in[0];
    const float* rW = (const float*)d_in[1];
    const float* rg = (const float*)d_in[2];
    const float* rb = (const float*)d_in[3];
    const float* rm = (const float*)d_in[4];
    const float* rv = (const float*)d_in[5];
    const float* qW = (const float*)d_in[6];
    const float* qg = (const float*)d_in[7];
    const float* qb = (const float*)d_in[8];
    const float* qm = (const float*)d_in[9];
    const float* qv = (const float*)d_in[10];
    const float* kW = (const float*)d_in[11];
    const float* kg = (const float*)d_in[12];
    const float* kb = (const float*)d_in[13];
    const float* km = (const float*)d_in[14];
    const float* kv = (const float*)d_in[15];
    const float* vW = (const float*)d_in[16];
    const float* vg = (const float*)d_in[17];
    const float* vb = (const float*)d_in[18];
    const float* vm = (const float*)d_in[19];
    const float* vvp = (const float*)d_in[20];
    const float* uW = (const float*)d_in[21];
    const float* ug = (const float*)d_in[22];
    const float* ub = (const float*)d_in[23];
    const float* um = (const float*)d_in[24];
    const float* uv = (const float*)d_in[25];

    float *f, *q, *k, *v, *attn, *upd;
    cudaGetSymbolAddress((void**)&f,    g_f);
    cudaGetSymbolAddress((void**)&q,    g_q);
    cudaGetSymbolAddress((void**)&k,    g_kk);
    cudaGetSymbolAddress((void**)&v,    g_v);
    cudaGetSymbolAddress((void**)&attn, g_attn);
    cudaGetSymbolAddress((void**)&upd,  g_upd);

    const long sF = 512L * 4096;          // per-batch stride of f/q/k/v/upd
    const long sX = 2048L * 4096;         // per-batch stride of feature / out
    const long sS = 4096L * 4096;         // per-batch stride of attn
    dim3 blk(256);

    // 1) f = relu(bn(rW @ feature))            M=512 N=4096 K=2048   [split]
    gemm_tc<0,1,1,0,1><<<dim3(32,4,4), blk>>>(rW, 0, 2048,
                                              feature, sX, 4096,
                                              nullptr, 0,
                                              f, sF, 4096,
                                              rg, rb, rm, rv, 2048);
    // 2) q,k,v from f                          M=512 N=4096 K=512    [split]
    gemm_tc<0,1,1,0,1><<<dim3(32,4,4), blk>>>(qW, 0, 512, f, sF, 4096, nullptr, 0,
                                              q, sF, 4096, qg, qb, qm, qv, 512);
    gemm_tc<0,1,1,0,1><<<dim3(32,4,4), blk>>>(kW, 0, 512, f, sF, 4096, nullptr, 0,
                                              k, sF, 4096, kg, kb, km, kv, 512);
    gemm_tc<0,1,1,0,1><<<dim3(32,4,4), blk>>>(vW, 0, 512, f, sF, 4096, nullptr, 0,
                                              v, sF, 4096, vg, vb, vm, vvp, 512);
    // 3) S[n][m] = sum_c q[c][n] k[c][m]       M=4096 N=4096 K=512   [split]
    gemm_tc<1,1,0,0,1><<<dim3(32,32,4), blk>>>(q, sF, 4096,
                                               k, sF, 4096,
                                               nullptr, 0,
                                               attn, sS, 4096,
                                               nullptr, nullptr, nullptr, nullptr, 512);
    // 4) softmax rows
    softmax_k<<<4 * 4096, 256>>>(attn);
    // 5) upd[c][n] = sum_m v[c][m] attn[n][m]  M=512 N=4096 K=4096   [plain tf32]
    gemm_tc<0,0,0,0,0><<<dim3(32,4,4), blk>>>(v, sF, 4096,
                                              attn, sS, 4096,
                                              nullptr, 0,
                                              upd, sF, 4096,
                                              nullptr, nullptr, nullptr, nullptr, 4096);
    // 6) out = relu(bn(uW @ (f + upd)))        M=2048 N=4096 K=512   [plain tf32]
    gemm_tc<0,1,1,1,0><<<dim3(32,16,4), blk>>>(uW, 0, 512,
                                               f, sF, 4096,
                                               upd, sF,
                                               (float*)d_out, sX, 4096,
                                               ug, ub, um, uv, 512);
}